// round 4
// baseline (speedup 1.0000x reference)
#include <cuda_runtime.h>
#include <math.h>

#define D       20
#define K1      30
#define KP      32          // padded K1
#define NRELP1  201
#define NTIME   365
#define NLAYERS 3
#define MAXN    1000000
#define T       256         // edges per block
#define HS      21          // h / bias shared stride (odd -> conflict-free)
#define PS      33          // pbc shared stride (odd -> conflict-free)

// ---------------- scratch (device globals; no runtime allocation) ----------------
__device__ __align__(16) float g_buf0[MAXN * D];            // 80 MB
__device__ __align__(16) float g_buf1[MAXN * D];            // 80 MB
__device__ __align__(16) float g_PbP[NRELP1 * KP];          // rela part of att MLP (padded)
__device__ __align__(16) float g_PcP[NRELP1 * KP];          // qrel part of att MLP (padded)
__device__ __align__(16) float g_RW[3 * NRELP1 * D];        // rela @ W_s^T
__device__ __align__(16) float g_TW[3 * NTIME * D];         // time @ W_s^T
__device__ __align__(16) float g_S0[NRELP1 * NRELP1];       // layer-0 sigmoid scores

__device__ __forceinline__ void red_add_f32(float* addr, float v) {
    asm volatile(
        "{ .reg .u64 p; cvta.to.global.u64 p, %0;\n\t"
        "  red.global.add.f32 [p], %1; }\n\t"
        :: "l"(addr), "f"(v) : "memory");
}

__device__ __forceinline__ float leaky(float x) { return x > 0.f ? x : 0.01f * x; }

// ---------------- table precompute ----------------
__global__ void k_tables(const float* __restrict__ rela, const float* __restrict__ tem,
                         const float* __restrict__ w1,
                         const float* __restrict__ wp, const float* __restrict__ wn,
                         const float* __restrict__ wf)
{
    int i = blockIdx.x * blockDim.x + threadIdx.x;
    const int NPB = NRELP1 * KP;                 // 6432
    const int NRW = 3 * NRELP1 * D;              // 12060
    const int NTW = 3 * NTIME * D;               // 21900
    if (i < NPB) {
        int r = i / KP, k = i % KP;
        float a = 0.f;
        if (k < K1) {
            #pragma unroll
            for (int j = 0; j < D; j++) a = fmaf(rela[r * D + j], w1[k * (3 * D) + D + j], a);
        }
        g_PbP[i] = a;
    } else if (i < 2 * NPB) {
        int t = i - NPB;
        int r = t / KP, k = t % KP;
        float a = 0.f;
        if (k < K1) {
            #pragma unroll
            for (int j = 0; j < D; j++) a = fmaf(rela[r * D + j], w1[k * (3 * D) + 2 * D + j], a);
        }
        g_PcP[t] = a;
    } else if (i < 2 * NPB + NRW) {
        int t = i - 2 * NPB;
        int s = t / (NRELP1 * D);
        int rem = t % (NRELP1 * D);
        int r = rem / D, o = rem % D;
        const float* W = (s == 0) ? wp : ((s == 1) ? wn : wf);
        float a = 0.f;
        #pragma unroll
        for (int j = 0; j < D; j++) a = fmaf(rela[r * D + j], W[o * D + j], a);
        g_RW[t] = a;
    } else if (i < 2 * NPB + NRW + NTW) {
        int t = i - 2 * NPB - NRW;
        int s = t / (NTIME * D);
        int rem = t % (NTIME * D);
        int tt = rem / D, o = rem % D;
        const float* W = (s == 0) ? wp : ((s == 1) ? wn : wf);
        float a = 0.f;
        #pragma unroll
        for (int j = 0; j < D; j++) a = fmaf(tem[tt * D + j], W[o * D + j], a);
        g_TW[t] = a;
    }
}

// layer-0 score table: h_src = 0 -> score depends only on (rel, qrel)
__global__ void k_s0(const float* __restrict__ w2)
{
    int i = blockIdx.x * blockDim.x + threadIdx.x;
    if (i >= NRELP1 * NRELP1) return;
    int r = i / NRELP1, q = i % NRELP1;
    float s = 0.f;
    #pragma unroll
    for (int k = 0; k < K1; k++) {
        float a = g_PbP[r * KP + k] + g_PcP[q * KP + k];
        a = fmaxf(a, 0.f);
        s = fmaf(a, w2[k], s);
    }
    g_S0[i] = 1.f / (1.f + __expf(-s));
}

// ---------------- layer 0: hidden == 0, staged gather/scale/scatter ----------------
__global__ __launch_bounds__(256) void k_edge0(
    const int* __restrict__ rel, const int* __restrict__ qrel,
    const int* __restrict__ rtime, const int* __restrict__ dst,
    float* __restrict__ hout, int E)
{
    __shared__ float s_sc[T];
    __shared__ int s_rwb[T], s_twb[T], s_dn[T];
    int tid = threadIdx.x;
    int e = blockIdx.x * T + tid;
    bool valid = e < E;
    int r = 0, q = 0, rt = 0, dn = 0;
    if (valid) { r = rel[e]; q = qrel[e]; rt = rtime[e]; dn = dst[e]; }
    int sel = (rt > 0) ? 2 : ((rt == 0) ? 1 : 0);
    int ta = rt < 0 ? -rt : rt;
    s_sc[tid]  = valid ? g_S0[r * NRELP1 + q] : 0.f;
    s_rwb[tid] = (sel * NRELP1 + r) * D;
    s_twb[tid] = (sel * NTIME + ta) * D;
    s_dn[tid]  = dn * D;
    __syncthreads();

    for (int i = tid; i < T * D; i += 256) {
        int ee = i / D, j = i - ee * D;
        float v = s_sc[ee] * (g_RW[s_rwb[ee] + j] + g_TW[s_twb[ee] + j]);
        red_add_f32(hout + s_dn[ee] + j, v);
    }
}

// ---------------- generic layer: staged gathers, 1 edge/thread compute ----------------
__global__ __launch_bounds__(256, 2) void k_edge(
    const int* __restrict__ src, const int* __restrict__ dst,
    const int* __restrict__ rel, const int* __restrict__ qrel,
    const int* __restrict__ rtime,
    const float* __restrict__ hin, float* __restrict__ hout,
    const float* __restrict__ w1, const float* __restrict__ w2,
    const float* __restrict__ wp, const float* __restrict__ wn,
    const float* __restrict__ wf, int E)
{
    extern __shared__ float sm[];
    float* sw1a  = sm;                       // [K1*D] = 600
    float* sw2s  = sm + 600;                 // [KP]   = 32
    float* sW    = sm + 632;                 // [3*D*D]= 1200
    float* s_pbc = sm + 1832;                // [T*PS] = 8448
    float* s_h   = s_pbc + T * PS;           // [T*HS] = 5376
    float* s_bm  = s_h + T * HS;             // [T*HS] bias, then msg overlay
    int*   s_int = (int*)(s_bm + T * HS);
    int* s_hb  = s_int;
    int* s_pbb = s_int + T;
    int* s_pcb = s_int + 2 * T;
    int* s_rwb = s_int + 3 * T;
    int* s_twb = s_int + 4 * T;
    int* s_dn  = s_int + 5 * T;

    int tid = threadIdx.x;

    // weights -> shared
    for (int i = tid; i < K1 * D; i += 256)
        sw1a[i] = w1[(i / D) * (3 * D) + (i % D)];
    if (tid < KP) sw2s[tid] = (tid < K1) ? w2[tid] : 0.f;
    for (int i = tid; i < 3 * D * D; i += 256) {
        int s = i / (D * D); int rm = i % (D * D);
        sW[i] = ((s == 0) ? wp : ((s == 1) ? wn : wf))[rm];
    }

    // index prep: 1 edge per thread
    int e = blockIdx.x * T + tid;
    bool valid = e < E;
    int sn = 0, dn = 0, r = 0, q = 0, rt = 0;
    if (valid) { sn = src[e]; dn = dst[e]; r = rel[e]; q = qrel[e]; rt = rtime[e]; }
    int sel = (rt > 0) ? 2 : ((rt == 0) ? 1 : 0);
    int ta = rt < 0 ? -rt : rt;
    s_hb[tid]  = sn * D;
    s_pbb[tid] = r * KP;
    s_pcb[tid] = q * KP;
    s_rwb[tid] = (sel * NRELP1 + r) * D;
    s_twb[tid] = (sel * NTIME + ta) * D;
    s_dn[tid]  = dn * D;
    __syncthreads();

    // stage pbc = Pb[rel] + Pc[qrel] (1 line per row per table)
    #pragma unroll 4
    for (int i = tid; i < T * KP; i += 256) {
        int ee = i >> 5, k = i & 31;
        s_pbc[ee * PS + k] = g_PbP[s_pbb[ee] + k] + g_PcP[s_pcb[ee] + k];
    }
    // stage h (leaky fused)
    #pragma unroll 4
    for (int i = tid; i < T * D; i += 256) {
        int ee = i / D, j = i - ee * D;
        s_h[ee * HS + j] = leaky(hin[s_hb[ee] + j]);
    }
    // stage bias = RW + TW
    #pragma unroll 4
    for (int i = tid; i < T * D; i += 256) {
        int ee = i / D, j = i - ee * D;
        s_bm[ee * HS + j] = g_RW[s_rwb[ee] + j] + g_TW[s_twb[ee] + j];
    }
    __syncthreads();

    // compute own edge from registers + shared broadcasts
    float h[D];
    #pragma unroll
    for (int j = 0; j < D; j++) h[j] = s_h[tid * HS + j];

    float sacc = 0.f;
    #pragma unroll
    for (int k = 0; k < K1; k++) {
        float a = s_pbc[tid * PS + k];
        #pragma unroll
        for (int j = 0; j < D; j++) a = fmaf(h[j], sw1a[k * D + j], a);
        sacc = fmaf(fmaxf(a, 0.f), sw2s[k], sacc);
    }
    float score = valid ? (1.f / (1.f + __expf(-sacc))) : 0.f;

    const float* Wb = sW + sel * D * D;
    #pragma unroll
    for (int i = 0; i < D; i++) {
        float acc = s_bm[tid * HS + i];
        #pragma unroll
        for (int j = 0; j < D; j++) acc = fmaf(h[j], Wb[i * D + j], acc);
        s_bm[tid * HS + i] = score * acc;      // msg overlay (own slots only)
    }
    __syncthreads();

    // cooperative scatter (line-granular)
    for (int i = tid; i < T * D; i += 256) {
        int ee = i / D, j = i - ee * D;
        red_add_f32(hout + s_dn[ee] + j, s_bm[ee * HS + j]);
    }
}

// ---------------- final: leaky -> dot(w_cls) + b -> scatter ----------------
__global__ __launch_bounds__(256) void k_final(
    const float* __restrict__ hin, const int* __restrict__ nb,
    const int* __restrict__ ne, const float* __restrict__ wcls,
    const float* __restrict__ bcls, const int* __restrict__ pne,
    float* __restrict__ out, int n)
{
    int i = blockIdx.x * blockDim.x + threadIdx.x;
    if (i >= n) return;
    const float4* hp = (const float4*)(hin + (size_t)i * D);
    float acc = bcls[0];
    #pragma unroll
    for (int g = 0; g < D / 4; g++) {
        float4 v = hp[g];
        acc = fmaf(leaky(v.x), __ldg(wcls + 4 * g + 0), acc);
        acc = fmaf(leaky(v.y), __ldg(wcls + 4 * g + 1), acc);
        acc = fmaf(leaky(v.z), __ldg(wcls + 4 * g + 2), acc);
        acc = fmaf(leaky(v.w), __ldg(wcls + 4 * g + 3), acc);
    }
    long long idx = (long long)nb[i] * (long long)pne[0] + (long long)ne[i];
    out[idx] = acc;
}

// ---------------- host ----------------
extern "C" void kernel_launch(void* const* d_in, const int* in_sizes, int n_in,
                              void* d_out, int out_size)
{
    const int*   src   = (const int*)d_in[0];
    const int*   dst   = (const int*)d_in[1];
    const int*   rel   = (const int*)d_in[2];
    const int*   qrel  = (const int*)d_in[3];
    const int*   rtime = (const int*)d_in[4];
    const int*   nb    = (const int*)d_in[5];
    const int*   ne    = (const int*)d_in[6];
    const float* rela  = (const float*)d_in[7];
    const float* tem   = (const float*)d_in[8];
    const float* w1    = (const float*)d_in[9];
    const float* w2    = (const float*)d_in[10];
    const float* wp    = (const float*)d_in[11];
    const float* wn    = (const float*)d_in[12];
    const float* wf    = (const float*)d_in[13];
    const float* wcls  = (const float*)d_in[14];
    const float* bcls  = (const float*)d_in[15];
    const int*   pne   = (const int*)d_in[17];

    int E  = in_sizes[0] / NLAYERS;
    int Nn = in_sizes[5];

    float *b0, *b1;
    cudaGetSymbolAddress((void**)&b0, g_buf0);
    cudaGetSymbolAddress((void**)&b1, g_buf1);
    size_t bufBytes = (size_t)Nn * D * sizeof(float);

    // dynamic shared for k_edge: 21032 floats + 1536 ints = 90272 bytes
    const int SMEM_EDGE = (1832 + T * PS + 2 * T * HS) * 4 + 6 * T * 4;
    static int smem_set = 0;
    if (!smem_set) {
        cudaFuncSetAttribute(k_edge, cudaFuncAttributeMaxDynamicSharedMemorySize, SMEM_EDGE);
        smem_set = 1;
    }

    // precompute tables (independent of hidden state)
    const int NTAB = 2 * NRELP1 * KP + 3 * NRELP1 * D + 3 * NTIME * D;
    k_tables<<<(NTAB + 255) / 256, 256>>>(rela, tem, w1, wp, wn, wf);
    k_s0<<<(NRELP1 * NRELP1 + 255) / 256, 256>>>(w2);

    int gE = (E + T - 1) / T;

    // layer 0 (h = 0): accumulate into buf1
    cudaMemsetAsync(b1, 0, bufBytes);
    k_edge0<<<gE, 256>>>(rel, qrel, rtime, dst, b1, E);

    // layer 1: read act(buf1) -> accumulate buf0
    cudaMemsetAsync(b0, 0, bufBytes);
    k_edge<<<gE, 256, SMEM_EDGE>>>(src + E, dst + E, rel + E, qrel + E, rtime + E,
                                   b1, b0, w1, w2, wp, wn, wf, E);

    // layer 2: read act(buf0) -> accumulate buf1
    cudaMemsetAsync(b1, 0, bufBytes);
    k_edge<<<gE, 256, SMEM_EDGE>>>(src + 2 * E, dst + 2 * E, rel + 2 * E, qrel + 2 * E,
                                   rtime + 2 * E, b0, b1, w1, w2, wp, wn, wf, E);

    // output: zero then scatter
    cudaMemsetAsync(d_out, 0, (size_t)out_size * sizeof(float));
    k_final<<<(Nn + 255) / 256, 256>>>(b1, nb, ne, wcls, bcls, pne, (float*)d_out, Nn);
}

// round 5
// speedup vs baseline: 2.1530x; 2.1530x over previous
#include <cuda_runtime.h>
#include <math.h>

#define D       20
#define DP      32          // padded row stride (128B)
#define K1      30
#define NRELP1  201
#define NTIME   365
#define NLAYERS 3
#define MAXN    1000000

// ---------------- scratch (device globals; no runtime allocation) ----------------
__device__ __align__(16) float g_buf0[MAXN * D];                 // 80 MB
__device__ __align__(16) float g_buf1[MAXN * D];                 // 80 MB
__device__ __align__(16) float g_PbP[NRELP1 * DP];               // rela part of att MLP
__device__ __align__(16) float g_PcP[NRELP1 * DP];               // qrel part of att MLP
__device__ __align__(16) float g_PBC[NRELP1 * NRELP1 * DP];      // Pb[r]+Pc[q], 5.2 MB
__device__ __align__(16) float g_RWp[3 * NRELP1 * DP];           // rela @ W_s^T (padded)
__device__ __align__(16) float g_TWp[3 * NTIME * DP];            // time @ W_s^T (padded)
__device__ __align__(16) float g_S0[NRELP1 * NRELP1];            // layer-0 scores
__device__ __align__(16) float g_HA[MAXN * DP];                  // leaky(h) @ w1a^T, 128 MB
__device__ __align__(16) float g_HT[3 * MAXN * D];               // leaky(h) @ W_s^T, 240 MB

__device__ __forceinline__ void red_add_v4(float* addr, float a, float b, float c, float d) {
    asm volatile(
        "{ .reg .u64 p; cvta.to.global.u64 p, %0;\n\t"
        "  red.global.add.v4.f32 [p], {%1, %2, %3, %4}; }\n\t"
        :: "l"(addr), "f"(a), "f"(b), "f"(c), "f"(d) : "memory");
}

__device__ __forceinline__ float leaky(float x) { return x > 0.f ? x : 0.01f * x; }

// ---------------- small-table precompute ----------------
__global__ void k_tables(const float* __restrict__ rela, const float* __restrict__ tem,
                         const float* __restrict__ w1,
                         const float* __restrict__ wp, const float* __restrict__ wn,
                         const float* __restrict__ wf)
{
    int i = blockIdx.x * blockDim.x + threadIdx.x;
    const int NPB  = NRELP1 * DP;       // 6432
    const int NRW  = 3 * NRELP1 * DP;   // 19296
    const int NTW  = 3 * NTIME * DP;    // 35040
    if (i < NPB) {                                     // PbP
        int r = i / DP, k = i % DP;
        float a = 0.f;
        if (k < K1) {
            #pragma unroll
            for (int j = 0; j < D; j++) a = fmaf(rela[r * D + j], w1[k * (3 * D) + D + j], a);
        }
        g_PbP[i] = a;
    } else if (i < 2 * NPB) {                          // PcP
        int t = i - NPB;
        int r = t / DP, k = t % DP;
        float a = 0.f;
        if (k < K1) {
            #pragma unroll
            for (int j = 0; j < D; j++) a = fmaf(rela[r * D + j], w1[k * (3 * D) + 2 * D + j], a);
        }
        g_PcP[t] = a;
    } else if (i < 2 * NPB + NRW) {                    // RWp (zero-padded cols 20..31)
        int t = i - 2 * NPB;
        int s = t / (NRELP1 * DP);
        int rem = t % (NRELP1 * DP);
        int r = rem / DP, o = rem % DP;
        float a = 0.f;
        if (o < D) {
            const float* W = (s == 0) ? wp : ((s == 1) ? wn : wf);
            #pragma unroll
            for (int j = 0; j < D; j++) a = fmaf(rela[r * D + j], W[o * D + j], a);
        }
        g_RWp[t] = a;
    } else if (i < 2 * NPB + NRW + NTW) {              // TWp
        int t = i - 2 * NPB - NRW;
        int s = t / (NTIME * DP);
        int rem = t % (NTIME * DP);
        int tt = rem / DP, o = rem % DP;
        float a = 0.f;
        if (o < D) {
            const float* W = (s == 0) ? wp : ((s == 1) ? wn : wf);
            #pragma unroll
            for (int j = 0; j < D; j++) a = fmaf(tem[tt * D + j], W[o * D + j], a);
        }
        g_TWp[t] = a;
    }
}

// PBC[r][q][k] = PbP[r][k] + PcP[q][k]
__global__ void k_pbc()
{
    int i = blockIdx.x * blockDim.x + threadIdx.x;
    if (i >= NRELP1 * NRELP1 * DP) return;
    int k = i & (DP - 1);
    int rq = i >> 5;
    int q = rq % NRELP1, r = rq / NRELP1;
    g_PBC[i] = g_PbP[r * DP + k] + g_PcP[q * DP + k];
}

// layer-0 score table: h_src = 0 -> score depends only on (rel, qrel)
__global__ void k_s0(const float* __restrict__ w2)
{
    int i = blockIdx.x * blockDim.x + threadIdx.x;
    if (i >= NRELP1 * NRELP1) return;
    int r = i / NRELP1, q = i % NRELP1;
    float s = 0.f;
    #pragma unroll
    for (int k = 0; k < K1; k++) {
        float a = g_PbP[r * DP + k] + g_PcP[q * DP + k];
        a = fmaxf(a, 0.f);
        s = fmaf(a, w2[k], s);
    }
    g_S0[i] = 1.f / (1.f + __expf(-s));
}

// ---------------- node precompute: HA = leaky(h)@w1a^T, HT[s] = leaky(h)@W_s^T ----------
__global__ __launch_bounds__(256) void k_node(
    const float* __restrict__ hin,
    const float* __restrict__ w1, const float* __restrict__ wp,
    const float* __restrict__ wn, const float* __restrict__ wf, int Nn)
{
    __shared__ float s_w1a[K1 * D];           // 2.4 KB
    __shared__ float s_W[3 * D * D];          // 4.8 KB
    __shared__ float s_o[256 * 33];           // 33.8 KB, reused: h-stage / HA / HT
    int tid = threadIdx.x;
    for (int i = tid; i < K1 * D; i += 256)
        s_w1a[i] = w1[(i / D) * (3 * D) + (i % D)];
    for (int i = tid; i < 3 * D * D; i += 256) {
        int s = i / (D * D), rm = i % (D * D);
        s_W[i] = ((s == 0) ? wp : ((s == 1) ? wn : wf))[rm];
    }
    int base = blockIdx.x * 256;
    int nblk = Nn - base; if (nblk > 256) nblk = 256;

    // stage h coalesced into s_o (stride 21), fuse leaky
    for (int f = tid; f < nblk * D; f += 256) {
        float v = hin[(size_t)base * D + f];
        s_o[(f / D) * 21 + (f % D)] = leaky(v);
    }
    __syncthreads();
    float h[D];
    #pragma unroll
    for (int j = 0; j < D; j++) h[j] = s_o[tid * 21 + j];
    __syncthreads();

    // HA: 30 outputs per node, staged stride 33, coalesced store
    #pragma unroll 1
    for (int o = 0; o < K1; o++) {
        float a = 0.f;
        #pragma unroll
        for (int j = 0; j < D; j++) a = fmaf(h[j], s_w1a[o * D + j], a);
        s_o[tid * 33 + o] = a;
    }
    s_o[tid * 33 + 30] = 0.f;
    s_o[tid * 33 + 31] = 0.f;
    __syncthreads();
    for (int f = tid; f < nblk * DP; f += 256)
        g_HA[(size_t)base * DP + f] = s_o[(f >> 5) * 33 + (f & 31)];

    // HT per sel: 20 outputs, staged stride 21, coalesced store
    for (int sel = 0; sel < 3; sel++) {
        __syncthreads();
        #pragma unroll 1
        for (int o = 0; o < D; o++) {
            float a = 0.f;
            #pragma unroll
            for (int j = 0; j < D; j++) a = fmaf(h[j], s_W[sel * D * D + o * D + j], a);
            s_o[tid * 21 + o] = a;
        }
        __syncthreads();
        for (int f = tid; f < nblk * D; f += 256)
            g_HT[(size_t)sel * MAXN * D + (size_t)base * D + f] = s_o[(f / D) * 21 + f % D];
    }
}

// ---------------- layer 0: h == 0, 8 lanes per edge ----------------
__global__ __launch_bounds__(256) void k_edge0(
    const int* __restrict__ rel, const int* __restrict__ qrel,
    const int* __restrict__ rtime, const int* __restrict__ dst,
    float* __restrict__ hout, int E)
{
    int tid = threadIdx.x, lane = tid & 31, wid = tid >> 5;
    int grp = lane >> 3, sub = lane & 7;
    int base = (blockIdx.x * 8 + wid) * 32;
    #pragma unroll
    for (int it = 0; it < 8; it++) {
        int ew = base + it * 4 + grp;
        bool valid = ew < E;
        int ei = valid ? ew : 0;
        int dn = dst[ei], r = rel[ei], q = qrel[ei], rt = rtime[ei];
        int sel = (rt > 0) ? 2 : ((rt == 0) ? 1 : 0);
        int ta = rt < 0 ? -rt : rt;
        float score = g_S0[r * NRELP1 + q];
        if (valid && sub < 5) {
            float4 rw = *(const float4*)(g_RWp + (sel * NRELP1 + r) * DP + sub * 4);
            float4 tw = *(const float4*)(g_TWp + (sel * NTIME + ta) * DP + sub * 4);
            red_add_v4(hout + (size_t)dn * D + sub * 4,
                       score * (rw.x + tw.x), score * (rw.y + tw.y),
                       score * (rw.z + tw.z), score * (rw.w + tw.w));
        }
    }
}

// ---------------- generic layer: 8 lanes per edge, table-only ----------------
__global__ __launch_bounds__(256) void k_edge(
    const int* __restrict__ src, const int* __restrict__ dst,
    const int* __restrict__ rel, const int* __restrict__ qrel,
    const int* __restrict__ rtime, const float* __restrict__ w2,
    float* __restrict__ hout, int E)
{
    int tid = threadIdx.x, lane = tid & 31, wid = tid >> 5;
    int grp = lane >> 3, sub = lane & 7;
    float w2r0 = (sub * 4 + 0 < K1) ? w2[sub * 4 + 0] : 0.f;
    float w2r1 = (sub * 4 + 1 < K1) ? w2[sub * 4 + 1] : 0.f;
    float w2r2 = (sub * 4 + 2 < K1) ? w2[sub * 4 + 2] : 0.f;
    float w2r3 = (sub * 4 + 3 < K1) ? w2[sub * 4 + 3] : 0.f;
    int base = (blockIdx.x * 8 + wid) * 32;
    #pragma unroll
    for (int it = 0; it < 8; it++) {
        int ew = base + it * 4 + grp;
        bool valid = ew < E;
        int ei = valid ? ew : 0;
        int sn = src[ei], dn = dst[ei], r = rel[ei], q = qrel[ei], rt = rtime[ei];
        int sel = (rt > 0) ? 2 : ((rt == 0) ? 1 : 0);
        int ta = rt < 0 ? -rt : rt;
        // attention: 8 lanes cover the 32-wide padded row
        float4 ha = *(const float4*)(g_HA + (size_t)sn * DP + sub * 4);
        float4 pb = *(const float4*)(g_PBC + (size_t)(r * NRELP1 + q) * DP + sub * 4);
        float p = fmaxf(ha.x + pb.x, 0.f) * w2r0;
        p = fmaf(fmaxf(ha.y + pb.y, 0.f), w2r1, p);
        p = fmaf(fmaxf(ha.z + pb.z, 0.f), w2r2, p);
        p = fmaf(fmaxf(ha.w + pb.w, 0.f), w2r3, p);
        p += __shfl_xor_sync(0xffffffffu, p, 1);
        p += __shfl_xor_sync(0xffffffffu, p, 2);
        p += __shfl_xor_sync(0xffffffffu, p, 4);
        float score = 1.f / (1.f + __expf(-p));
        // message: lanes 0..4 cover 20 floats
        if (valid && sub < 5) {
            float4 ht = *(const float4*)(g_HT + ((size_t)sel * MAXN + sn) * D + sub * 4);
            float4 rw = *(const float4*)(g_RWp + (sel * NRELP1 + r) * DP + sub * 4);
            float4 tw = *(const float4*)(g_TWp + (sel * NTIME + ta) * DP + sub * 4);
            red_add_v4(hout + (size_t)dn * D + sub * 4,
                       score * (ht.x + rw.x + tw.x), score * (ht.y + rw.y + tw.y),
                       score * (ht.z + rw.z + tw.z), score * (ht.w + rw.w + tw.w));
        }
    }
}

// ---------------- final: leaky -> dot(w_cls) + b -> scatter ----------------
__global__ __launch_bounds__(256) void k_final(
    const float* __restrict__ hin, const int* __restrict__ nb,
    const int* __restrict__ ne, const float* __restrict__ wcls,
    const float* __restrict__ bcls, const int* __restrict__ pne,
    float* __restrict__ out, int n)
{
    int i = blockIdx.x * blockDim.x + threadIdx.x;
    if (i >= n) return;
    const float4* hp = (const float4*)(hin + (size_t)i * D);
    float acc = bcls[0];
    #pragma unroll
    for (int g = 0; g < D / 4; g++) {
        float4 v = hp[g];
        acc = fmaf(leaky(v.x), __ldg(wcls + 4 * g + 0), acc);
        acc = fmaf(leaky(v.y), __ldg(wcls + 4 * g + 1), acc);
        acc = fmaf(leaky(v.z), __ldg(wcls + 4 * g + 2), acc);
        acc = fmaf(leaky(v.w), __ldg(wcls + 4 * g + 3), acc);
    }
    long long idx = (long long)nb[i] * (long long)pne[0] + (long long)ne[i];
    out[idx] = acc;
}

// ---------------- host ----------------
extern "C" void kernel_launch(void* const* d_in, const int* in_sizes, int n_in,
                              void* d_out, int out_size)
{
    const int*   src   = (const int*)d_in[0];
    const int*   dst   = (const int*)d_in[1];
    const int*   rel   = (const int*)d_in[2];
    const int*   qrel  = (const int*)d_in[3];
    const int*   rtime = (const int*)d_in[4];
    const int*   nb    = (const int*)d_in[5];
    const int*   ne    = (const int*)d_in[6];
    const float* rela  = (const float*)d_in[7];
    const float* tem   = (const float*)d_in[8];
    const float* w1    = (const float*)d_in[9];
    const float* w2    = (const float*)d_in[10];
    const float* wp    = (const float*)d_in[11];
    const float* wn    = (const float*)d_in[12];
    const float* wf    = (const float*)d_in[13];
    const float* wcls  = (const float*)d_in[14];
    const float* bcls  = (const float*)d_in[15];
    const int*   pne   = (const int*)d_in[17];

    int E  = in_sizes[0] / NLAYERS;
    int Nn = in_sizes[5];

    float *b0, *b1;
    cudaGetSymbolAddress((void**)&b0, g_buf0);
    cudaGetSymbolAddress((void**)&b1, g_buf1);
    size_t bufBytes = (size_t)Nn * D * sizeof(float);

    // small tables
    const int NTAB = 2 * NRELP1 * DP + 3 * NRELP1 * DP + 3 * NTIME * DP;
    k_tables<<<(NTAB + 255) / 256, 256>>>(rela, tem, w1, wp, wn, wf);
    k_s0<<<(NRELP1 * NRELP1 + 255) / 256, 256>>>(w2);
    k_pbc<<<(NRELP1 * NRELP1 * DP + 255) / 256, 256>>>();

    int gE = (E + 255) / 256;          // 256 edges per block (8 warps x 32)
    int gN = (Nn + 255) / 256;

    // layer 0 (h = 0): accumulate into buf1
    cudaMemsetAsync(b1, 0, bufBytes);
    k_edge0<<<gE, 256>>>(rel, qrel, rtime, dst, b1, E);

    // layer 1: node precompute from buf1, edges -> buf0
    k_node<<<gN, 256>>>(b1, w1, wp, wn, wf, Nn);
    cudaMemsetAsync(b0, 0, bufBytes);
    k_edge<<<gE, 256>>>(src + E, dst + E, rel + E, qrel + E, rtime + E, w2, b0, E);

    // layer 2: node precompute from buf0, edges -> buf1
    k_node<<<gN, 256>>>(b0, w1, wp, wn, wf, Nn);
    cudaMemsetAsync(b1, 0, bufBytes);
    k_edge<<<gE, 256>>>(src + 2 * E, dst + 2 * E, rel + 2 * E, qrel + 2 * E, rtime + 2 * E,
                        w2, b1, E);

    // output: zero then scatter
    cudaMemsetAsync(d_out, 0, (size_t)out_size * sizeof(float));
    k_final<<<(Nn + 255) / 256, 256>>>(b1, nb, ne, wcls, bcls, pne, (float*)d_out, Nn);
}